// round 8
// baseline (speedup 1.0000x reference)
#include <cuda_runtime.h>
#include <math.h>
#include <stdint.h>

#define N_NODES 8192
#define IN_F    256
#define OUT_F   64
#define QSPLIT  8
#define KQ      (N_NODES / QSPLIT)     // 1024 j per CTA
#define CH      32                     // j per chunk (4 ksteps of 8)
#define NCH     (KQ / CH)              // 32 chunks
#define MT      128                    // rows per CTA (4 warps x 32)
#define TPB     128                    // 4 warps
#define PS      132
#define BSLOTS  1152                   // 4 ksteps * 9 nblk * 32 lanes (float4)
#define BBYTES  (BSLOTS * 16)          // 18432 B per chunk stage
#define NSTG    4                      // cp.async ring stages
#define SMEM_K2 (NSTG * BBYTES + 512)  // 74240 B dynamic smem
#define FONE    0x3F800000u

// ---------------- static device scratch ------------------------------------
__device__ float  g_f1[N_NODES], g_E1[N_NODES], g_Q1[N_NODES], g_f2v[N_NODES];
// fragment-ordered B: [jstep][nblk(8)+den(1)][lane] = {he0,he1,hq0,hq1}
__device__ float4 g_Bpack[N_NODES / 8][9][32];            // 4.7 MB
__device__ float  g_pD[QSPLIT][N_NODES][PS];              // ~35 MB partials

// ---------------- helpers ----------------------------------------------------
__device__ __forceinline__ float to_tf32(float x) {
    uint32_t u; asm("cvt.rna.tf32.f32 %0, %1;" : "=r"(u) : "f"(x));
    return __uint_as_float(u);
}
__device__ __forceinline__ uint32_t smem_u32(const void* p) {
    uint32_t a;
    asm("{ .reg .u64 t; cvta.to.shared.u64 t, %1; cvt.u32.u64 %0, t; }"
        : "=r"(a) : "l"(p));
    return a;
}
__device__ __forceinline__ void mma8(float* d, uint32_t a0, uint32_t a1,
                                     uint32_t a2, uint32_t a3,
                                     uint32_t b0, uint32_t b1) {
    asm volatile(
        "mma.sync.aligned.m16n8k8.row.col.f32.tf32.tf32.f32 "
        "{%0,%1,%2,%3}, {%4,%5,%6,%7}, {%8,%9}, {%0,%1,%2,%3};"
        : "+f"(d[0]), "+f"(d[1]), "+f"(d[2]), "+f"(d[3])
        : "r"(a0), "r"(a1), "r"(a2), "r"(a3), "r"(b0), "r"(b1));
}
#define BITF(w, sh) (((((w) >> (sh)) & 1u)) ? FONE : 0u)
#define CP16(sdst, gsrc) \
    asm volatile("cp.async.cg.shared.global [%0], [%1], 16;" \
                 :: "r"(sdst), "l"(gsrc) : "memory")
#define CP_COMMIT() asm volatile("cp.async.commit_group;" ::: "memory")
#define CP_WAIT2()  asm volatile("cp.async.wait_group 2;" ::: "memory")

// ---------------- kernel 1: h = X@W, scalars + fragment-packed B -----------
__global__ void k_h(const float* __restrict__ X, const float* __restrict__ W,
                    const float* __restrict__ a) {
    int warp = threadIdx.x >> 5, lane = threadIdx.x & 31;
    int row  = blockIdx.x * 8 + warp;
    const float* x0 = X + (size_t)row * IN_F;

    float acc0 = 0.f, acc1 = 0.f;
    #pragma unroll 4
    for (int k = 0; k < IN_F; k += 4) {
        float4 xv = *(const float4*)(x0 + k);     // lane-uniform broadcast
        const float* xp = (const float*)&xv;
        #pragma unroll
        for (int kk = 0; kk < 4; kk++) {
            float w0 = __ldg(W + (k + kk) * OUT_F + lane);
            float w1 = __ldg(W + (k + kk) * OUT_F + 32 + lane);
            acc0 = fmaf(xp[kk], w0, acc0);
            acc1 = fmaf(xp[kk], w1, acc1);
        }
    }

    float p1 = acc0 * __ldg(a + lane)      + acc1 * __ldg(a + 32 + lane);
    float p2 = acc0 * __ldg(a + 64 + lane) + acc1 * __ldg(a + 96 + lane);
    #pragma unroll
    for (int o = 16; o > 0; o >>= 1) {
        p1 += __shfl_xor_sync(0xffffffffu, p1, o);
        p2 += __shfl_xor_sync(0xffffffffu, p2, o);
    }
    float e2 = expf(p2), q2 = expf(0.2f * p2);
    int s = row >> 3, cp = row & 3, half = (row >> 2) & 1;

    {   // he/hq fragment slot for d = lane
        float* bb = (float*)&g_Bpack[s][lane >> 3][((lane & 7) << 2) | cp];
        bb[half]     = to_tf32(acc0 * e2);
        bb[2 + half] = to_tf32(acc0 * q2);
    }
    {   // d = lane + 32
        int d = lane + 32;
        float* bb = (float*)&g_Bpack[s][d >> 3][((d & 7) << 2) | cp];
        bb[half]     = to_tf32(acc1 * e2);
        bb[2 + half] = to_tf32(acc1 * q2);
    }
    if ((lane & 3) == cp) {   // den slot (nblk 8)
        float* bd = (float*)&g_Bpack[s][8][lane];
        bd[half]     = to_tf32(e2);
        bd[2 + half] = to_tf32(q2);
    }
    if (lane == 0) {
        g_f1[row]  = p1;
        g_E1[row]  = expf(p1);
        g_Q1[row]  = expf(0.2f * p1);
        g_f2v[row] = p2;
    }
}

// ---------------- kernel 2: binary-mask tf32 mma.sync GEMM ------------------
// 4 warps x 32 rows. A = 0/1 masks from coalesced adj ballots, SOFTWARE-
// PIPELINED one chunk ahead so adj LDG latency hides behind the previous
// chunk's MMAs. B via 4-stage cp.async ring; one __syncthreads per chunk.
__global__ void __launch_bounds__(TPB, 2)
k_attn(const int* __restrict__ adj) {
    extern __shared__ char dsm[];
    float4* smB = (float4*)dsm;                  // NSTG stages, contiguous
    float*  s_f1 = (float*)(dsm + NSTG * BBYTES);

    int t = threadIdx.x, lane = t & 31, wid = t >> 5;
    int g = lane >> 2, c = lane & 3;
    int strip = blockIdx.x * MT;
    int q = blockIdx.y, jq = q * KQ;

    uint32_t smb = smem_u32(dsm);
    const char* bsrc = (const char*)&g_Bpack[jq >> 3][0][0];

    // prologue: prefetch chunks 0 and 1
    #pragma unroll
    for (int pc = 0; pc < 2; pc++) {
        uint32_t d0 = smb + pc * BBYTES;
        const char* s0 = bsrc + (size_t)pc * BBYTES;
        for (int i = t; i < BSLOTS; i += TPB)
            CP16(d0 + i * 16, s0 + (size_t)i * 16);
        CP_COMMIT();
    }
    if (t < MT) s_f1[t] = g_f1[strip + t];
    __syncthreads();                              // s_f1 visible

    float aP[2][9][4], aN[2][9][4];
    #pragma unroll
    for (int m = 0; m < 2; m++)
        #pragma unroll
        for (int b = 0; b < 9; b++)
            #pragma unroll
            for (int v = 0; v < 4; v++) { aP[m][b][v] = 0.f; aN[m][b][v] = 0.f; }

    const int* ap0 = adj + (size_t)(strip + wid * 32) * N_NODES + jq + lane;

    // producer for chunk 0 (masks live in registers)
    unsigned Pc[4], Nc[4];
    {
        float f2l = g_f2v[jq + lane];
        const int* ap = ap0;
        #pragma unroll
        for (int m = 0; m < 4; m++) { Pc[m] = 0u; Nc[m] = 0u; }
        #pragma unroll
        for (int rr = 0; rr < 32; rr++) {
            int av = ap[(size_t)rr * N_NODES];
            float f1r = s_f1[wid * 32 + rr];
            bool nz  = (av != 0);
            bool pos = (f1r + f2l) >= 0.f;
            unsigned Pm = __ballot_sync(0xffffffffu, nz && pos);
            unsigned Nm = __ballot_sync(0xffffffffu, nz && !pos);
            if ((rr & 7) == g) { Pc[rr >> 3] = Pm; Nc[rr >> 3] = Nm; }
        }
        #pragma unroll
        for (int m = 0; m < 4; m++) { Pc[m] >>= c; Nc[m] >>= c; }
    }

    for (int ch = 0; ch < NCH; ch++) {
        int stg = ch & (NSTG - 1);

        // (a) prefetch B(ch+2); ALWAYS commit (group counting)
        if (ch + 2 < NCH) {
            uint32_t d0 = smb + ((ch + 2) & (NSTG - 1)) * BBYTES;
            const char* s0 = bsrc + (size_t)(ch + 2) * BBYTES;
            for (int i = t; i < BSLOTS; i += TPB)
                CP16(d0 + i * 16, s0 + (size_t)i * 16);
        }
        CP_COMMIT();

        // (b) producer for chunk ch+1 (overlaps with MMA(ch) below)
        unsigned Pn[4] = {0,0,0,0}, Nn[4] = {0,0,0,0};
        if (ch + 1 < NCH) {
            float f2l = g_f2v[jq + (ch + 1) * CH + lane];
            const int* ap = ap0 + (ch + 1) * CH;
            #pragma unroll
            for (int rr = 0; rr < 32; rr++) {
                int av = ap[(size_t)rr * N_NODES];
                float f1r = s_f1[wid * 32 + rr];
                bool nz  = (av != 0);
                bool pos = (f1r + f2l) >= 0.f;
                unsigned Pm = __ballot_sync(0xffffffffu, nz && pos);
                unsigned Nm = __ballot_sync(0xffffffffu, nz && !pos);
                if ((rr & 7) == g) { Pn[rr >> 3] = Pm; Nn[rr >> 3] = Nm; }
            }
            #pragma unroll
            for (int m = 0; m < 4; m++) { Pn[m] >>= c; Nn[m] >>= c; }
        }

        // (c)(d) chunk ch resident + visible
        CP_WAIT2();
        __syncthreads();

        // (e) MMA on stage stg with the pre-built masks for chunk ch
        const float4* bbase = smB + stg * BSLOTS + lane;
        #pragma unroll
        for (int s = 0; s < 4; s++) {
            unsigned sh = 8 * s;
            uint32_t pa[2][4], na[2][4];
            #pragma unroll
            for (int m = 0; m < 2; m++) {
                pa[m][0] = BITF(Pc[2*m],  sh);     pa[m][1] = BITF(Pc[2*m+1], sh);
                pa[m][2] = BITF(Pc[2*m],  sh + 4); pa[m][3] = BITF(Pc[2*m+1], sh + 4);
                na[m][0] = BITF(Nc[2*m],  sh);     na[m][1] = BITF(Nc[2*m+1], sh);
                na[m][2] = BITF(Nc[2*m],  sh + 4); na[m][3] = BITF(Nc[2*m+1], sh + 4);
            }
            const float4* bp = bbase + s * 9 * 32;
            #pragma unroll
            for (int b = 0; b < 9; b++) {
                float4 f = bp[b * 32];
                uint32_t be0 = __float_as_uint(f.x), be1 = __float_as_uint(f.y);
                uint32_t bq0 = __float_as_uint(f.z), bq1 = __float_as_uint(f.w);
                if (b == 8 && g != 0) { be0 = be1 = bq0 = bq1 = 0u; }
                #pragma unroll
                for (int m = 0; m < 2; m++) {
                    mma8(aP[m][b], pa[m][0], pa[m][1], pa[m][2], pa[m][3], be0, be1);
                    mma8(aN[m][b], na[m][0], na[m][1], na[m][2], na[m][3], bq0, bq1);
                }
            }
        }

        // rotate pipelined masks
        #pragma unroll
        for (int m = 0; m < 4; m++) { Pc[m] = Pn[m]; Nc[m] = Nn[m]; }
    }

    // ---- epilogue: store fragments to partials ----
    #pragma unroll
    for (int m = 0; m < 2; m++) {
        int r0 = strip + wid * 32 + 16 * m + g, r1 = r0 + 8;
        float* p0 = &g_pD[q][r0][0];
        float* p1 = &g_pD[q][r1][0];
        #pragma unroll
        for (int b = 0; b < 8; b++) {
            int col = 8 * b + 2 * c;
            *(float2*)(p0 + col)      = make_float2(aP[m][b][0], aP[m][b][1]);
            *(float2*)(p1 + col)      = make_float2(aP[m][b][2], aP[m][b][3]);
            *(float2*)(p0 + 64 + col) = make_float2(aN[m][b][0], aN[m][b][1]);
            *(float2*)(p1 + 64 + col) = make_float2(aN[m][b][2], aN[m][b][3]);
        }
        if (c == 0) {   // den lives in column 0 of nblk 8
            p0[128] = aP[m][8][0];  p0[129] = aN[m][8][0];
            p1[128] = aP[m][8][2];  p1[129] = aN[m][8][2];
        }
    }
}

// ---------------- kernel 3: combine splits, divide, ELU --------------------
__global__ void k_final(float* __restrict__ out) {
    int row = blockIdx.x;
    int d = threadIdx.x;                 // 64 threads
    float e1 = g_E1[row], q1 = g_Q1[row];
    float n1 = 0.f, n2 = 0.f, de = 0.f, dq = 0.f;
    #pragma unroll
    for (int q = 0; q < QSPLIT; q++) {
        n1 += g_pD[q][row][d];
        n2 += g_pD[q][row][64 + d];
        de += g_pD[q][row][128];
        dq += g_pD[q][row][129];
    }
    float num = e1 * n1 + q1 * n2;
    float den = e1 * de + q1 * dq;
    float v = num / den;
    out[(size_t)row * OUT_F + d] = (v > 0.f) ? v : expm1f(v);
}

// ---------------- launch ----------------------------------------------------
extern "C" void kernel_launch(void* const* d_in, const int* in_sizes, int n_in,
                              void* d_out, int out_size) {
    const float* X = nullptr; const int* adj = nullptr;
    const float* W = nullptr; const float* a = nullptr;
    for (int i = 0; i < n_in; i++) {
        switch (in_sizes[i]) {
            case N_NODES * IN_F:    X   = (const float*)d_in[i]; break;
            case N_NODES * N_NODES: adj = (const int*)  d_in[i]; break;
            case IN_F * OUT_F:      W   = (const float*)d_in[i]; break;
            case 2 * OUT_F:         a   = (const float*)d_in[i]; break;
        }
    }
    cudaFuncSetAttribute(k_attn, cudaFuncAttributeMaxDynamicSharedMemorySize,
                         SMEM_K2);
    k_h<<<N_NODES / 8, 256>>>(X, W, a);
    dim3 g2(N_NODES / MT, QSPLIT);
    k_attn<<<g2, TPB, SMEM_K2>>>(adj);
    k_final<<<N_NODES, OUT_F>>>((float*)d_out);
}

// round 9
// speedup vs baseline: 1.2837x; 1.2837x over previous
#include <cuda_runtime.h>
#include <cuda_fp16.h>
#include <math.h>
#include <stdint.h>

#define N_NODES 8192
#define IN_F    256
#define OUT_F   64
#define QSPLIT  4
#define KQ      (N_NODES / QSPLIT)     // 2048 j per CTA
#define CH      32                     // j per chunk (2 ksteps of 16)
#define NCH     (KQ / CH)              // 64 chunks
#define MT      128                    // rows per CTA (4 warps x 32)
#define TPB     128                    // 4 warps
#define PS      132
#define BSLOTS  576                    // 2 ksteps * 9 nblk * 32 lanes (float4)
#define BBYTES  (BSLOTS * 16)          // 9216 B per chunk stage
#define NSTG    4                      // cp.async ring stages
#define SMEM_K2 (NSTG * BBYTES + 512)  // 37376 B dynamic smem
#define HESCALE 0.03125f               // 2^-5: keeps he inside fp16 range
#define HEINV   32.0f

// ---------------- static device scratch ------------------------------------
__device__ float  g_f1[N_NODES], g_E1[N_NODES], g_Q1[N_NODES], g_f2v[N_NODES];
// fp16 fragment-ordered B: [jstep16][nblk8+den][lane][8 halves]
//   halves: [0..3] he {reg0.i0, reg0.i1, reg1.i0, reg1.i1}, [4..7] hq same
__device__ __half g_Bh[N_NODES / 16][9][32][8];           // 2.36 MB
__device__ float  g_pD[QSPLIT][N_NODES][PS];              // partials

// ---------------- helpers ----------------------------------------------------
__device__ __forceinline__ uint32_t smem_u32(const void* p) {
    uint32_t a;
    asm("{ .reg .u64 t; cvta.to.shared.u64 t, %1; cvt.u32.u64 %0, t; }"
        : "=r"(a) : "l"(p));
    return a;
}
// two mask bits (sh, sh+1) -> packed half2 {0|1, 0|1}
__device__ __forceinline__ uint32_t bit2h(unsigned w, int sh) {
    unsigned b = w >> sh;
    return ((b & 1u) ? 0x3C00u : 0u) | ((b & 2u) ? 0x3C000000u : 0u);
}
__device__ __forceinline__ void mma16(float* d, uint32_t a0, uint32_t a1,
                                      uint32_t a2, uint32_t a3,
                                      uint32_t b0, uint32_t b1) {
    asm volatile(
        "mma.sync.aligned.m16n8k16.row.col.f32.f16.f16.f32 "
        "{%0,%1,%2,%3}, {%4,%5,%6,%7}, {%8,%9}, {%0,%1,%2,%3};"
        : "+f"(d[0]), "+f"(d[1]), "+f"(d[2]), "+f"(d[3])
        : "r"(a0), "r"(a1), "r"(a2), "r"(a3), "r"(b0), "r"(b1));
}
#define CP16(sdst, gsrc) \
    asm volatile("cp.async.cg.shared.global [%0], [%1], 16;" \
                 :: "r"(sdst), "l"(gsrc) : "memory")
#define CP_COMMIT() asm volatile("cp.async.commit_group;" ::: "memory")
#define CP_WAIT2()  asm volatile("cp.async.wait_group 2;" ::: "memory")

// ---------------- kernel 1: h = X@W, scalars + fp16 fragment-packed B ------
__global__ void k_h(const float* __restrict__ X, const float* __restrict__ W,
                    const float* __restrict__ a) {
    int warp = threadIdx.x >> 5, lane = threadIdx.x & 31;
    int row  = blockIdx.x * 8 + warp;
    const float* x0 = X + (size_t)row * IN_F;

    float acc0 = 0.f, acc1 = 0.f;
    #pragma unroll 4
    for (int k = 0; k < IN_F; k += 4) {
        float4 xv = *(const float4*)(x0 + k);     // lane-uniform broadcast
        const float* xp = (const float*)&xv;
        #pragma unroll
        for (int kk = 0; kk < 4; kk++) {
            float w0 = __ldg(W + (k + kk) * OUT_F + lane);
            float w1 = __ldg(W + (k + kk) * OUT_F + 32 + lane);
            acc0 = fmaf(xp[kk], w0, acc0);
            acc1 = fmaf(xp[kk], w1, acc1);
        }
    }

    float p1 = acc0 * __ldg(a + lane)      + acc1 * __ldg(a + 32 + lane);
    float p2 = acc0 * __ldg(a + 64 + lane) + acc1 * __ldg(a + 96 + lane);
    #pragma unroll
    for (int o = 16; o > 0; o >>= 1) {
        p1 += __shfl_xor_sync(0xffffffffu, p1, o);
        p2 += __shfl_xor_sync(0xffffffffu, p2, o);
    }
    float e2 = expf(p2), q2 = expf(0.2f * p2);

    // fp16 m16n8k16 B-fragment slot for row j=row:
    //   reg = (j>>3)&1, c = (j&7)>>1, i = j&1, lane_t = (n&7)*4 + c
    int s16 = row >> 4;
    int reg = (row >> 3) & 1, cc = (row & 7) >> 1, ii = row & 1;
    int slot = reg * 2 + ii;
    {   // d = lane
        __half* bp = g_Bh[s16][lane >> 3][((lane & 7) << 2) | cc];
        bp[slot]     = __float2half_rn(acc0 * e2 * HESCALE);
        bp[4 + slot] = __float2half_rn(acc0 * q2);
    }
    {   // d = lane + 32
        int d = lane + 32;
        __half* bp = g_Bh[s16][d >> 3][((d & 7) << 2) | cc];
        bp[slot]     = __float2half_rn(acc1 * e2 * HESCALE);
        bp[4 + slot] = __float2half_rn(acc1 * q2);
    }
    if (lane == 0) {   // den slot: nblk 8, column n=0 -> lane_t = cc
        __half* bd = g_Bh[s16][8][cc];
        bd[slot]     = __float2half_rn(e2 * HESCALE);
        bd[4 + slot] = __float2half_rn(q2);
        g_f1[row]  = p1;
        g_E1[row]  = expf(p1);
        g_Q1[row]  = expf(0.2f * p1);
        g_f2v[row] = p2;
    }
}

// ---------------- kernel 2: binary-mask fp16 m16n8k16 GEMM ------------------
// 4 warps x 32 rows (2 m16 tiles/warp). A = exact 0/1 fp16 masks built from
// coalesced adj ballots (leaky-ReLU sign folded in). k16 per MMA halves the
// MMA count vs tf32 k8. B via 4-stage cp.async ring; one barrier per chunk.
__global__ void __launch_bounds__(TPB, 2)
k_attn(const int* __restrict__ adj) {
    extern __shared__ char dsm[];
    float4* smB = (float4*)dsm;                  // NSTG stages, contiguous
    float*  s_f1 = (float*)(dsm + NSTG * BBYTES);

    int t = threadIdx.x, lane = t & 31, wid = t >> 5;
    int g = lane >> 2, c = lane & 3;
    int strip = blockIdx.x * MT;
    int q = blockIdx.y, jq = q * KQ;

    uint32_t smb = smem_u32(dsm);
    const char* bsrc = (const char*)&g_Bh[jq >> 4][0][0][0];

    // prologue: prefetch chunks 0 and 1
    #pragma unroll
    for (int pc = 0; pc < 2; pc++) {
        uint32_t d0 = smb + pc * BBYTES;
        const char* s0 = bsrc + (size_t)pc * BBYTES;
        for (int i = t; i < BSLOTS; i += TPB)
            CP16(d0 + i * 16, s0 + (size_t)i * 16);
        CP_COMMIT();
    }
    if (t < MT) s_f1[t] = g_f1[strip + t];
    __syncthreads();                              // s_f1 visible

    float aP[2][9][4], aN[2][9][4];
    #pragma unroll
    for (int m = 0; m < 2; m++)
        #pragma unroll
        for (int b = 0; b < 9; b++)
            #pragma unroll
            for (int v = 0; v < 4; v++) { aP[m][b][v] = 0.f; aN[m][b][v] = 0.f; }

    const int* ap0 = adj + (size_t)(strip + wid * 32) * N_NODES + jq + lane;

    for (int ch = 0; ch < NCH; ch++) {
        int stg = ch & (NSTG - 1);

        // (a) prefetch B(ch+2); ALWAYS commit (group counting)
        if (ch + 2 < NCH) {
            uint32_t d0 = smb + ((ch + 2) & (NSTG - 1)) * BBYTES;
            const char* s0 = bsrc + (size_t)(ch + 2) * BBYTES;
            for (int i = t; i < BSLOTS; i += TPB)
                CP16(d0 + i * 16, s0 + (size_t)i * 16);
        }
        CP_COMMIT();

        // (b) producer: adj ballots for this warp's 32 rows (coalesced).
        // Raw 32-bit row words; bit j = column j of chunk.
        float f2l = g_f2v[jq + ch * CH + lane];
        const int* ap = ap0 + ch * CH;
        unsigned P[4] = {0,0,0,0}, Nn[4] = {0,0,0,0};
        #pragma unroll
        for (int rr = 0; rr < 32; rr++) {
            int av = ap[(size_t)rr * N_NODES];
            float f1r = s_f1[wid * 32 + rr];
            bool nz  = (av != 0);
            bool pos = (f1r + f2l) >= 0.f;
            unsigned Pm = __ballot_sync(0xffffffffu, nz && pos);
            unsigned Nm = __ballot_sync(0xffffffffu, nz && !pos);
            if ((rr & 7) == g) { P[rr >> 3] = Pm; Nn[rr >> 3] = Nm; }
        }

        // (c)(d) chunk ch resident + visible
        CP_WAIT2();
        __syncthreads();

        // (e) MMA: 2 ksteps x 9 nblk x {P,N} x 2 mtiles = 72 m16n8k16
        const float4* bbase = smB + stg * BSLOTS + lane;
        #pragma unroll
        for (int s = 0; s < 2; s++) {
            int sh = (s << 4) + (c << 1);
            uint32_t pa[2][4], na[2][4];
            #pragma unroll
            for (int m = 0; m < 2; m++) {
                pa[m][0] = bit2h(P[2*m],   sh);     pa[m][1] = bit2h(P[2*m+1], sh);
                pa[m][2] = bit2h(P[2*m],   sh + 8); pa[m][3] = bit2h(P[2*m+1], sh + 8);
                na[m][0] = bit2h(Nn[2*m],  sh);     na[m][1] = bit2h(Nn[2*m+1], sh);
                na[m][2] = bit2h(Nn[2*m],  sh + 8); na[m][3] = bit2h(Nn[2*m+1], sh + 8);
            }
            const float4* bp = bbase + s * 9 * 32;
            #pragma unroll
            for (int b = 0; b < 9; b++) {
                float4 f = bp[b * 32];
                uint32_t be0 = __float_as_uint(f.x), be1 = __float_as_uint(f.y);
                uint32_t bq0 = __float_as_uint(f.z), bq1 = __float_as_uint(f.w);
                if (b == 8 && g != 0) { be0 = be1 = bq0 = bq1 = 0u; }
                #pragma unroll
                for (int m = 0; m < 2; m++) {
                    mma16(aP[m][b], pa[m][0], pa[m][1], pa[m][2], pa[m][3], be0, be1);
                    mma16(aN[m][b], na[m][0], na[m][1], na[m][2], na[m][3], bq0, bq1);
                }
            }
        }
    }

    // ---- epilogue: store fragments to partials ----
    #pragma unroll
    for (int m = 0; m < 2; m++) {
        int r0 = strip + wid * 32 + 16 * m + g, r1 = r0 + 8;
        float* p0 = &g_pD[q][r0][0];
        float* p1 = &g_pD[q][r1][0];
        #pragma unroll
        for (int b = 0; b < 8; b++) {
            int col = 8 * b + 2 * c;
            *(float2*)(p0 + col)      = make_float2(aP[m][b][0], aP[m][b][1]);
            *(float2*)(p1 + col)      = make_float2(aP[m][b][2], aP[m][b][3]);
            *(float2*)(p0 + 64 + col) = make_float2(aN[m][b][0], aN[m][b][1]);
            *(float2*)(p1 + 64 + col) = make_float2(aN[m][b][2], aN[m][b][3]);
        }
        if (c == 0) {   // den lives in column 0 of nblk 8
            p0[128] = aP[m][8][0];  p0[129] = aN[m][8][0];
            p1[128] = aP[m][8][2];  p1[129] = aN[m][8][2];
        }
    }
}

// ---------------- kernel 3: combine splits, unscale, divide, ELU -----------
__global__ void k_final(float* __restrict__ out) {
    int row = blockIdx.x;
    int d = threadIdx.x;                 // 64 threads
    float e1 = g_E1[row], q1 = g_Q1[row];
    float n1 = 0.f, n2 = 0.f, de = 0.f, dq = 0.f;
    #pragma unroll
    for (int q = 0; q < QSPLIT; q++) {
        n1 += g_pD[q][row][d];
        n2 += g_pD[q][row][64 + d];
        de += g_pD[q][row][128];
        dq += g_pD[q][row][129];
    }
    n1 *= HEINV; de *= HEINV;            // undo exact 2^-5 he/E2 scaling
    float num = e1 * n1 + q1 * n2;
    float den = e1 * de + q1 * dq;
    float v = num / den;
    out[(size_t)row * OUT_F + d] = (v > 0.f) ? v : expm1f(v);
}

// ---------------- launch ----------------------------------------------------
extern "C" void kernel_launch(void* const* d_in, const int* in_sizes, int n_in,
                              void* d_out, int out_size) {
    const float* X = nullptr; const int* adj = nullptr;
    const float* W = nullptr; const float* a = nullptr;
    for (int i = 0; i < n_in; i++) {
        switch (in_sizes[i]) {
            case N_NODES * IN_F:    X   = (const float*)d_in[i]; break;
            case N_NODES * N_NODES: adj = (const int*)  d_in[i]; break;
            case IN_F * OUT_F:      W   = (const float*)d_in[i]; break;
            case 2 * OUT_F:         a   = (const float*)d_in[i]; break;
        }
    }
    cudaFuncSetAttribute(k_attn, cudaFuncAttributeMaxDynamicSharedMemorySize,
                         SMEM_K2);
    k_h<<<N_NODES / 8, 256>>>(X, W, a);
    dim3 g2(N_NODES / MT, QSPLIT);
    k_attn<<<g2, TPB, SMEM_K2>>>(adj);
    k_final<<<N_NODES, OUT_F>>>((float*)d_out);
}